// round 8
// baseline (speedup 1.0000x reference)
#include <cuda_runtime.h>
#include <cuda_fp16.h>
#include <cstdint>

// Problem constants
constexpr int Dc = 2048, Rc = 256, NTOK = 16384;

// Scratch (no cudaMalloc allowed)
__device__ __half g_wiT[Rc * Dc];       // prepped weight_in,  transposed [N=R, K=D]
__device__ __half g_woT[Dc * Rc];       // prepped weight_out, transposed [N=D, K=R]

// ---------------------------------------------------------------------------
// Helpers
// ---------------------------------------------------------------------------
__device__ __forceinline__ uint32_t smem_u32(const void* p) {
    uint32_t a;
    asm("{ .reg .u64 t; cvta.to.shared.u64 t, %1; cvt.u32.u64 %0, t; }" : "=r"(a) : "l"(p));
    return a;
}

#define CP_ASYNC16(dst, src) asm volatile("cp.async.cg.shared.global [%0], [%1], 16;" :: "r"(dst), "l"(src))
#define CP_COMMIT()          asm volatile("cp.async.commit_group;" ::: "memory")
template <int N> __device__ __forceinline__ void cp_wait() {
    asm volatile("cp.async.wait_group %0;" :: "n"(N) : "memory");
}

__device__ __forceinline__ void ldsm4(uint32_t* r, uint32_t addr) {
    asm volatile("ldmatrix.sync.aligned.m8n8.x4.shared.b16 {%0,%1,%2,%3}, [%4];"
                 : "=r"(r[0]), "=r"(r[1]), "=r"(r[2]), "=r"(r[3]) : "r"(addr));
}
__device__ __forceinline__ void mma16816(float* d, const uint32_t* a,
                                         uint32_t b0, uint32_t b1) {
    asm volatile(
        "mma.sync.aligned.m16n8k16.row.col.f32.f16.f16.f32 "
        "{%0,%1,%2,%3}, {%4,%5,%6,%7}, {%8,%9}, {%0,%1,%2,%3};\n"
        : "+f"(d[0]), "+f"(d[1]), "+f"(d[2]), "+f"(d[3])
        : "r"(a[0]), "r"(a[1]), "r"(a[2]), "r"(a[3]), "r"(b0), "r"(b1));
}

// swizzled offset for (row, 16B-chunk cc):  row*128 + ((cc ^ (row&7)) << 4)
__device__ __forceinline__ uint32_t sw_off(int row, int cc) {
    return (uint32_t)(row * 128 + ((cc ^ (row & 7)) << 4));
}

// ---------------------------------------------------------------------------
// 2:4 soft-threshold prep for BOTH weights in one launch.
// Output TRANSPOSED to [N, K] fp16 (K-major). Groups of 4 along Nd (last dim).
// ---------------------------------------------------------------------------
__device__ __forceinline__ void prep_one(const float* __restrict__ W, float s,
                                         __half* __restrict__ Wt, int Kd, int Nd, int t)
{
    int nk = Kd >> 2;
    int k0 = (t % nk) << 2;
    int n0 = (t / nk) << 2;
    __half o[4][4];
    #pragma unroll
    for (int i = 0; i < 4; i++) {
        float4 w = *reinterpret_cast<const float4*>(W + (size_t)(k0 + i) * Nd + n0);
        float a0 = fabsf(w.x), a1 = fabsf(w.y), a2 = fabsf(w.z), a3 = fabsf(w.w);
        float lo01 = fminf(a0, a1), hi01 = fmaxf(a0, a1);
        float lo23 = fminf(a2, a3), hi23 = fmaxf(a2, a3);
        float th = fminf(fmaxf(lo01, lo23), fminf(hi01, hi23));
        o[i][0] = __float2half(copysignf(fmaxf(a0 - th, 0.f), w.x) * s);
        o[i][1] = __float2half(copysignf(fmaxf(a1 - th, 0.f), w.y) * s);
        o[i][2] = __float2half(copysignf(fmaxf(a2 - th, 0.f), w.z) * s);
        o[i][3] = __float2half(copysignf(fmaxf(a3 - th, 0.f), w.w) * s);
    }
    #pragma unroll
    for (int j = 0; j < 4; j++) {
        __half2 p0 = __halves2half2(o[0][j], o[1][j]);
        __half2 p1 = __halves2half2(o[2][j], o[3][j]);
        uint2 u;
        u.x = *reinterpret_cast<uint32_t*>(&p0);
        u.y = *reinterpret_cast<uint32_t*>(&p1);
        *reinterpret_cast<uint2*>(Wt + (size_t)(n0 + j) * Kd + k0) = u;
    }
}

__global__ void prep_both(const float* __restrict__ Wi, const float* __restrict__ si,
                          const float* __restrict__ Wo, const float* __restrict__ so,
                          __half* __restrict__ WiT, __half* __restrict__ WoT)
{
    if (blockIdx.x < 128) {
        int t = blockIdx.x * blockDim.x + threadIdx.x;
        prep_one(Wi, si[0], WiT, Dc, Rc, t);
    } else {
        int t = (blockIdx.x - 128) * blockDim.x + threadIdx.x;
        prep_one(Wo, so[0], WoT, Rc, Dc, t);
    }
}

// ---------------------------------------------------------------------------
// FUSED kernel: per CTA (64 rows m0..m0+64):
//   Phase 1: h[64,256] = fp16( x @ wiT^T + b_in )  -> kept in SMEM only
//   Phase 2: y[64,2048] = fp32( h @ woT^T + b_out ) streamed over 16 n-tiles
// SMEM (112KB, 2 CTAs/SM):
//   phase 1: A fp32-staged 2x8KB @0, B 3x32KB @16KB
//   h-stage: 4 k-chunks of 8KB @0 (written after final phase-1 sync)
//   phase 2: B ring 4x16KB @32KB
// ---------------------------------------------------------------------------
__global__ __launch_bounds__(256, 2) void fused_kernel(
    const float* __restrict__ X, const __half* __restrict__ WiT,
    const __half* __restrict__ WoT,
    const float* __restrict__ b_in, const float* __restrict__ b_out,
    float* __restrict__ Y)
{
    constexpr int KT1 = 2048 / 64;  // 32
    extern __shared__ char smem[];
    const uint32_t sb = smem_u32(smem);
    const int tid = threadIdx.x, wid = tid >> 5, lane = tid & 31;
    const int wm = wid >> 2, wn = wid & 3;   // 2 x 4 warps
    const int m0 = blockIdx.x * 64;
    const int g = lane >> 2, tc = (lane & 3) * 2;
    const int lhi = lane >> 4;

    // ============================ PHASE 1 ============================
    // warp tile 32x64 over CTA tile 64x256
    auto A1off = [&](int b) { return sb + b * 8192u; };
    auto B1off = [&](int s) { return sb + 16384u + s * 32768u; };

    float4 aR[4];
    const int arow = tid >> 2, aq = tid & 3;
    auto ldgA = [&](int kt) {
        const float* p = X + (size_t)(m0 + arow) * 2048 + kt * 64 + aq * 16;
        #pragma unroll
        for (int j = 0; j < 4; j++) aR[j] = *reinterpret_cast<const float4*>(p + j * 4);
    };
    auto stsA = [&](int b) {
        #pragma unroll
        for (int h16 = 0; h16 < 2; h16++) {
            __half2 h0 = __floats2half2_rn(aR[2*h16].x,   aR[2*h16].y);
            __half2 h1 = __floats2half2_rn(aR[2*h16].z,   aR[2*h16].w);
            __half2 h2 = __floats2half2_rn(aR[2*h16+1].x, aR[2*h16+1].y);
            __half2 h3 = __floats2half2_rn(aR[2*h16+1].z, aR[2*h16+1].w);
            uint32_t u0 = *reinterpret_cast<uint32_t*>(&h0);
            uint32_t u1 = *reinterpret_cast<uint32_t*>(&h1);
            uint32_t u2 = *reinterpret_cast<uint32_t*>(&h2);
            uint32_t u3 = *reinterpret_cast<uint32_t*>(&h3);
            uint32_t dst = A1off(b) + sw_off(arow, aq * 2 + h16);
            asm volatile("st.shared.v4.b32 [%0], {%1,%2,%3,%4};"
                         :: "r"(dst), "r"(u0), "r"(u1), "r"(u2), "r"(u3) : "memory");
        }
    };
    auto ldB1 = [&](int kt, int s) {
        #pragma unroll
        for (int i = 0; i < 8; i++) {
            int c = tid + i * 256, row = c >> 3, cc = c & 7;
            CP_ASYNC16(B1off(s) + sw_off(row, cc),
                       WiT + (size_t)row * 2048 + kt * 64 + cc * 8);
        }
    };

    float acc[2][8][4];
    #pragma unroll
    for (int mi = 0; mi < 2; mi++)
        #pragma unroll
        for (int nn = 0; nn < 8; nn++)
            #pragma unroll
            for (int j = 0; j < 4; j++) acc[mi][nn][j] = 0.f;

    uint32_t aB1[2], bB1[4]; int aX1[2], bX1[4];
    #pragma unroll
    for (int mi = 0; mi < 2; mi++) {
        int r = wm * 32 + mi * 16 + (lane & 15);
        aB1[mi] = (uint32_t)(r * 128); aX1[mi] = r & 7;
    }
    #pragma unroll
    for (int ni = 0; ni < 4; ni++) {
        int r = wn * 64 + ni * 16 + (lane & 15);
        bB1[ni] = (uint32_t)(r * 128); bX1[ni] = r & 7;
    }

    auto compute1 = [&](int ab, int bs) {
        const uint32_t Ab = A1off(ab), Bb = B1off(bs);
        #pragma unroll
        for (int ks = 0; ks < 4; ks++) {
            const int c = ks * 2 + lhi;
            uint32_t af[2][4], bf[4][4];
            #pragma unroll
            for (int mi = 0; mi < 2; mi++)
                ldsm4(af[mi], Ab + aB1[mi] + ((uint32_t)(c ^ aX1[mi]) << 4));
            #pragma unroll
            for (int ni = 0; ni < 4; ni++)
                ldsm4(bf[ni], Bb + bB1[ni] + ((uint32_t)(c ^ bX1[ni]) << 4));
            #pragma unroll
            for (int mi = 0; mi < 2; mi++)
                #pragma unroll
                for (int ni = 0; ni < 4; ni++) {
                    mma16816(acc[mi][2*ni],   af[mi], bf[ni][0], bf[ni][2]);
                    mma16816(acc[mi][2*ni+1], af[mi], bf[ni][1], bf[ni][3]);
                }
        }
    };

    ldgA(0); stsA(0);
    ldB1(0, 0); CP_COMMIT();
    ldB1(1, 1); CP_COMMIT();
    ldgA(1);

    for (int kt = 0; kt < KT1; kt++) {
        if (kt < KT1 - 1) cp_wait<1>(); else cp_wait<0>();
        __syncthreads();
        if (kt + 2 < KT1) { ldB1(kt + 2, (kt + 2) % 3); CP_COMMIT(); }
        compute1(kt & 1, kt % 3);
        if (kt + 1 < KT1) {
            stsA((kt + 1) & 1);
            if (kt + 2 < KT1) ldgA(kt + 2);
        }
    }
    __syncthreads();   // all phase-1 smem reads done

    // ====================== h-stage + phase-2 prefetch ======================
    // phase-2 B ring: 4 x 16KB at sb+32768 (disjoint from h-stage at sb+0..32KB)
    auto B2off = [&](int buf) { return sb + 32768u + buf * 16384u; };
    auto ldB2 = [&](int nt, int kt, int buf) {
        const int n0 = nt * 128;
        #pragma unroll
        for (int i = 0; i < 4; i++) {
            int c = tid + i * 256, row = c >> 3, cc = c & 7;
            CP_ASYNC16(B2off(buf) + sw_off(row, cc),
                       WoT + (size_t)(n0 + row) * 256 + kt * 64 + cc * 8);
        }
        CP_COMMIT();
    };
    ldB2(0, 0, 0); ldB2(0, 1, 1); ldB2(0, 2, 2);

    // h-stage: write acc (+bias, cvt fp16) into 4 A-chunk buffers at sb+0
    // thread element (rr, col): chunk kt=col>>6, addr = kt*8192 + sw(rr, (col&63)>>3) + (col&7)*2
    #pragma unroll
    for (int mi = 0; mi < 2; mi++)
        #pragma unroll
        for (int nn = 0; nn < 8; nn++) {
            int rr  = wm * 32 + mi * 16 + g;
            int col = wn * 64 + (nn >> 1) * 16 + (nn & 1) * 8 + tc;
            float b0 = b_in[col], b1 = b_in[col + 1];
            __half2 hA = __floats2half2_rn(acc[mi][nn][0] + b0, acc[mi][nn][1] + b1);
            __half2 hB = __floats2half2_rn(acc[mi][nn][2] + b0, acc[mi][nn][3] + b1);
            uint32_t base = (uint32_t)((col >> 6) * 8192) + (((uint32_t)col & 7u) << 1);
            uint32_t uA = *reinterpret_cast<uint32_t*>(&hA);
            uint32_t uB = *reinterpret_cast<uint32_t*>(&hB);
            asm volatile("st.shared.b32 [%0], %1;" ::
                "r"(sb + base + sw_off(rr, (col & 63) >> 3)), "r"(uA) : "memory");
            asm volatile("st.shared.b32 [%0], %1;" ::
                "r"(sb + base + sw_off(rr + 8, (col & 63) >> 3)), "r"(uB) : "memory");
        }
    __syncthreads();

    // ============================ PHASE 2 ============================
    // warp tile 32x32 over CTA tile 64x128; A = h-stage chunks at sb + kt*8192
    uint32_t aB2[2], bB2[2]; int aX2[2], bX2[2];
    #pragma unroll
    for (int mi = 0; mi < 2; mi++) {
        int r = wm * 32 + mi * 16 + (lane & 15);
        aB2[mi] = (uint32_t)(r * 128); aX2[mi] = r & 7;
    }
    #pragma unroll
    for (int ni = 0; ni < 2; ni++) {
        int r = wn * 32 + ni * 16 + (lane & 15);
        bB2[ni] = (uint32_t)(r * 128); bX2[ni] = r & 7;
    }

    float acc2[2][4][4];
    for (int nt = 0; nt < 16; nt++) {
        #pragma unroll
        for (int kt = 0; kt < 4; kt++) {
            const int t = nt * 4 + kt;
            cp_wait<2>();
            __syncthreads();
            if (t + 3 < 64) ldB2((t + 3) >> 2, (t + 3) & 3, (t + 3) & 3);
            if (kt == 0) {
                #pragma unroll
                for (int mi = 0; mi < 2; mi++)
                    #pragma unroll
                    for (int nn = 0; nn < 4; nn++)
                        #pragma unroll
                        for (int j = 0; j < 4; j++) acc2[mi][nn][j] = 0.f;
            }
            const uint32_t Ab = sb + kt * 8192u, Bb = B2off(t & 3);
            #pragma unroll
            for (int ks = 0; ks < 4; ks++) {
                const int c = ks * 2 + lhi;
                uint32_t af[2][4], bf[2][4];
                #pragma unroll
                for (int mi = 0; mi < 2; mi++)
                    ldsm4(af[mi], Ab + aB2[mi] + ((uint32_t)(c ^ aX2[mi]) << 4));
                #pragma unroll
                for (int ni = 0; ni < 2; ni++)
                    ldsm4(bf[ni], Bb + bB2[ni] + ((uint32_t)(c ^ bX2[ni]) << 4));
                #pragma unroll
                for (int mi = 0; mi < 2; mi++)
                    #pragma unroll
                    for (int ni = 0; ni < 2; ni++) {
                        mma16816(acc2[mi][2*ni],   af[mi], bf[ni][0], bf[ni][2]);
                        mma16816(acc2[mi][2*ni+1], af[mi], bf[ni][1], bf[ni][3]);
                    }
            }
            if (kt == 3) {
                // direct epilogue for n-tile nt (32B sector-aligned float2 stores)
                const int n0 = nt * 128;
                #pragma unroll
                for (int mi = 0; mi < 2; mi++)
                    #pragma unroll
                    for (int nn = 0; nn < 4; nn++) {
                        int row = m0 + wm * 32 + mi * 16 + g;
                        int col = n0 + wn * 32 + (nn >> 1) * 16 + (nn & 1) * 8 + tc;
                        float b0 = b_out[col], b1 = b_out[col + 1];
                        *reinterpret_cast<float2*>(Y + (size_t)row * 2048 + col) =
                            make_float2(acc2[mi][nn][0] + b0, acc2[mi][nn][1] + b1);
                        *reinterpret_cast<float2*>(Y + (size_t)(row + 8) * 2048 + col) =
                            make_float2(acc2[mi][nn][2] + b0, acc2[mi][nn][3] + b1);
                    }
            }
        }
    }
}

// ---------------------------------------------------------------------------
extern "C" void kernel_launch(void* const* d_in, const int* in_sizes, int n_in,
                              void* d_out, int out_size)
{
    const float* x     = (const float*)d_in[0];
    const float* w_in  = (const float*)d_in[1];
    const float* w_out = (const float*)d_in[2];
    const float* b_in  = (const float*)d_in[3];
    const float* b_out = (const float*)d_in[4];
    const float* s_in  = (const float*)d_in[5];
    const float* s_out = (const float*)d_in[6];

    __half *wiT, *woT;
    cudaGetSymbolAddress((void**)&wiT, g_wiT);
    cudaGetSymbolAddress((void**)&woT, g_woT);

    constexpr int SMEM = 16384 + 3 * 32768;  // 114688: phase-1 peak (phase-2 uses 96KB)
    cudaFuncSetAttribute(fused_kernel, cudaFuncAttributeMaxDynamicSharedMemorySize, SMEM);

    // Prep both weights: 2:4 soft-threshold + scale + transpose to [N,K] fp16
    prep_both<<<256, 256>>>(w_in, s_in, w_out, s_out, wiT, woT);

    // Fused: h stays in SMEM; y written directly. 256 CTAs, all resident (2/SM).
    fused_kernel<<<dim3(256), 256, SMEM>>>(x, wiT, woT, b_in, b_out, (float*)d_out);
}

// round 13
// speedup vs baseline: 1.0384x; 1.0384x over previous
#include <cuda_runtime.h>
#include <cuda_fp16.h>
#include <cstdint>

// Problem constants
constexpr int Dc = 2048, Rc = 256, NTOK = 16384;

// Scratch (no cudaMalloc allowed)
__device__ __half g_h[NTOK * Rc];       // intermediate h, fp16 (8 MB)
__device__ __half g_wiT[Rc * Dc];       // prepped weight_in,  transposed [N=R, K=D]
__device__ __half g_woT[Dc * Rc];       // prepped weight_out, transposed [N=D, K=R]

// ---------------------------------------------------------------------------
// Helpers
// ---------------------------------------------------------------------------
__device__ __forceinline__ uint32_t smem_u32(const void* p) {
    uint32_t a;
    asm("{ .reg .u64 t; cvta.to.shared.u64 t, %1; cvt.u32.u64 %0, t; }" : "=r"(a) : "l"(p));
    return a;
}

#define CP_ASYNC16(dst, src) asm volatile("cp.async.cg.shared.global [%0], [%1], 16;" :: "r"(dst), "l"(src))
#define CP_COMMIT()          asm volatile("cp.async.commit_group;" ::: "memory")
template <int N> __device__ __forceinline__ void cp_wait() {
    asm volatile("cp.async.wait_group %0;" :: "n"(N) : "memory");
}

__device__ __forceinline__ void ldsm4(uint32_t* r, uint32_t addr) {
    asm volatile("ldmatrix.sync.aligned.m8n8.x4.shared.b16 {%0,%1,%2,%3}, [%4];"
                 : "=r"(r[0]), "=r"(r[1]), "=r"(r[2]), "=r"(r[3]) : "r"(addr));
}
__device__ __forceinline__ void mma16816(float* d, const uint32_t* a,
                                         uint32_t b0, uint32_t b1) {
    asm volatile(
        "mma.sync.aligned.m16n8k16.row.col.f32.f16.f16.f32 "
        "{%0,%1,%2,%3}, {%4,%5,%6,%7}, {%8,%9}, {%0,%1,%2,%3};\n"
        : "+f"(d[0]), "+f"(d[1]), "+f"(d[2]), "+f"(d[3])
        : "r"(a[0]), "r"(a[1]), "r"(a[2]), "r"(a[3]), "r"(b0), "r"(b1));
}

// swizzled offset for (row, 16B-chunk cc):  row*128 + ((cc ^ (row&7)) << 4)
__device__ __forceinline__ uint32_t sw_off(int row, int cc) {
    return (uint32_t)(row * 128 + ((cc ^ (row & 7)) << 4));
}

// ---------------------------------------------------------------------------
// 2:4 soft-threshold helpers (groups of 4 along last dim of W[Kd,Nd]),
// output transposed to [Nd, Kd] fp16 K-major.
// ---------------------------------------------------------------------------
__device__ __forceinline__ void thresh4(float4 w, float s, __half* o) {
    float a0 = fabsf(w.x), a1 = fabsf(w.y), a2 = fabsf(w.z), a3 = fabsf(w.w);
    float lo01 = fminf(a0, a1), hi01 = fmaxf(a0, a1);
    float lo23 = fminf(a2, a3), hi23 = fmaxf(a2, a3);
    float th = fminf(fmaxf(lo01, lo23), fminf(hi01, hi23));
    o[0] = __float2half(copysignf(fmaxf(a0 - th, 0.f), w.x) * s);
    o[1] = __float2half(copysignf(fmaxf(a1 - th, 0.f), w.y) * s);
    o[2] = __float2half(copysignf(fmaxf(a2 - th, 0.f), w.z) * s);
    o[3] = __float2half(copysignf(fmaxf(a3 - th, 0.f), w.w) * s);
}

// Prep w_in ONLY, fine-grained: task = (k-pair, 4-col group). 65536 tasks.
__global__ void prep_wi_kernel(const float* __restrict__ W, const float* __restrict__ scale,
                               __half* __restrict__ Wt)
{
    int t = blockIdx.x * blockDim.x + threadIdx.x;   // 256 blocks x 256 thr
    int k0 = (t & 1023) << 1;                        // Kd/2 = 1024 k-pairs
    int n0 = (t >> 10) << 2;                         // Nd/4 = 64 col groups
    float s = scale[0];
    __half o0[4], o1[4];
    float4 w0 = *reinterpret_cast<const float4*>(W + (size_t)k0 * Rc + n0);
    float4 w1 = *reinterpret_cast<const float4*>(W + (size_t)(k0 + 1) * Rc + n0);
    thresh4(w0, s, o0);
    thresh4(w1, s, o1);
    #pragma unroll
    for (int j = 0; j < 4; j++) {
        __half2 p = __halves2half2(o0[j], o1[j]);
        *reinterpret_cast<__half2*>(Wt + (size_t)(n0 + j) * Dc + k0) = p;
    }
}

// Prep w_out as a coarse 4x4 task (used by rider CTAs inside gemm1)
__device__ __forceinline__ void prep_wo_task(const float* __restrict__ W, float s,
                                             __half* __restrict__ Wt, int t)
{
    int k0 = (t & 63) << 2;     // Rc/4 = 64
    int n0 = (t >> 6) << 2;     // Dc/4 = 512
    __half o[4][4];
    #pragma unroll
    for (int i = 0; i < 4; i++) {
        float4 w = *reinterpret_cast<const float4*>(W + (size_t)(k0 + i) * Dc + n0);
        thresh4(w, s, o[i]);
    }
    #pragma unroll
    for (int j = 0; j < 4; j++) {
        __half2 p0 = __halves2half2(o[0][j], o[1][j]);
        __half2 p1 = __halves2half2(o[2][j], o[3][j]);
        uint2 u;
        u.x = *reinterpret_cast<uint32_t*>(&p0);
        u.y = *reinterpret_cast<uint32_t*>(&p1);
        *reinterpret_cast<uint2*>(Wt + (size_t)(n0 + j) * Rc + k0) = u;
    }
}

// ---------------------------------------------------------------------------
// GEMM1 + rider prep: blocks [0,256) compute h; blocks [256,288) prep woT.
// GEMM1: h[16384,256] = fp16( x[16384,2048] @ wiT^T + b_in )
// CTA 64x256, BK=64, 8 warps (32x64 warp tile), 2 CTAs/SM.
// ---------------------------------------------------------------------------
__global__ __launch_bounds__(256, 2) void gemm1_kernel(
    const float* __restrict__ A, const __half* __restrict__ Bt,
    const float* __restrict__ bias, __half* __restrict__ C,
    const float* __restrict__ Wo, const float* __restrict__ so,
    __half* __restrict__ WoT)
{
    // ---- rider CTAs: prep w_out, then exit ----
    if (blockIdx.x >= 256) {
        const int base = (blockIdx.x - 256) * 256 + threadIdx.x;  // 8192 threads
        float s = so[0];
        #pragma unroll
        for (int i = 0; i < 4; i++)
            prep_wo_task(Wo, s, WoT, base + i * 8192);            // 32768 tasks
        return;
    }

    constexpr int KT = 2048 / 64;  // 32
    extern __shared__ char smem[];
    const uint32_t sb = smem_u32(smem);
    const int tid = threadIdx.x, wid = tid >> 5, lane = tid & 31;
    const int wm = wid >> 2, wn = wid & 3;   // 2 x 4 warps, warp tile 32x64
    const int m0 = blockIdx.x * 64;

    auto Aoff = [&](int b) { return sb + b * 8192u; };            // 2 x 8KB
    auto Boff = [&](int s) { return sb + 16384u + s * 32768u; };  // 3 x 32KB

    float4 aR[4];
    const int arow = tid >> 2, aq = tid & 3;
    auto ldgA = [&](int kt) {
        const float* p = A + (size_t)(m0 + arow) * 2048 + kt * 64 + aq * 16;
        #pragma unroll
        for (int j = 0; j < 4; j++) aR[j] = *reinterpret_cast<const float4*>(p + j * 4);
    };
    auto stsA = [&](int b) {
        #pragma unroll
        for (int h16 = 0; h16 < 2; h16++) {
            __half2 h0 = __floats2half2_rn(aR[2*h16].x,   aR[2*h16].y);
            __half2 h1 = __floats2half2_rn(aR[2*h16].z,   aR[2*h16].w);
            __half2 h2 = __floats2half2_rn(aR[2*h16+1].x, aR[2*h16+1].y);
            __half2 h3 = __floats2half2_rn(aR[2*h16+1].z, aR[2*h16+1].w);
            uint32_t u0 = *reinterpret_cast<uint32_t*>(&h0);
            uint32_t u1 = *reinterpret_cast<uint32_t*>(&h1);
            uint32_t u2 = *reinterpret_cast<uint32_t*>(&h2);
            uint32_t u3 = *reinterpret_cast<uint32_t*>(&h3);
            uint32_t dst = Aoff(b) + sw_off(arow, aq * 2 + h16);
            asm volatile("st.shared.v4.b32 [%0], {%1,%2,%3,%4};"
                         :: "r"(dst), "r"(u0), "r"(u1), "r"(u2), "r"(u3) : "memory");
        }
    };
    auto ldB = [&](int kt, int s) {
        #pragma unroll
        for (int i = 0; i < 8; i++) {
            int c = tid + i * 256, row = c >> 3, cc = c & 7;
            CP_ASYNC16(Boff(s) + sw_off(row, cc),
                       Bt + (size_t)row * 2048 + kt * 64 + cc * 8);
        }
    };

    float acc[2][8][4];
    #pragma unroll
    for (int mi = 0; mi < 2; mi++)
        #pragma unroll
        for (int nn = 0; nn < 8; nn++)
            #pragma unroll
            for (int j = 0; j < 4; j++) acc[mi][nn][j] = 0.f;

    uint32_t aBase[2], bBase[4]; int aX[2], bX[4];
    #pragma unroll
    for (int mi = 0; mi < 2; mi++) {
        int r = wm * 32 + mi * 16 + (lane & 15);
        aBase[mi] = (uint32_t)(r * 128); aX[mi] = r & 7;
    }
    #pragma unroll
    for (int ni = 0; ni < 4; ni++) {
        int r = wn * 64 + ni * 16 + (lane & 15);
        bBase[ni] = (uint32_t)(r * 128); bX[ni] = r & 7;
    }
    const int lhi = lane >> 4;

    auto compute = [&](int ab, int bs) {
        const uint32_t Ab = Aoff(ab), Bb = Boff(bs);
        #pragma unroll
        for (int ks = 0; ks < 4; ks++) {
            const int c = ks * 2 + lhi;
            uint32_t af[2][4], bf[4][4];
            #pragma unroll
            for (int mi = 0; mi < 2; mi++)
                ldsm4(af[mi], Ab + aBase[mi] + ((uint32_t)(c ^ aX[mi]) << 4));
            #pragma unroll
            for (int ni = 0; ni < 4; ni++)
                ldsm4(bf[ni], Bb + bBase[ni] + ((uint32_t)(c ^ bX[ni]) << 4));
            #pragma unroll
            for (int mi = 0; mi < 2; mi++)
                #pragma unroll
                for (int ni = 0; ni < 4; ni++) {
                    mma16816(acc[mi][2*ni],   af[mi], bf[ni][0], bf[ni][2]);
                    mma16816(acc[mi][2*ni+1], af[mi], bf[ni][1], bf[ni][3]);
                }
        }
    };

    ldgA(0); stsA(0);
    ldB(0, 0); CP_COMMIT();
    ldB(1, 1); CP_COMMIT();
    ldgA(1);

    for (int kt = 0; kt < KT; kt++) {
        if (kt < KT - 1) cp_wait<1>(); else cp_wait<0>();
        __syncthreads();
        if (kt + 2 < KT) { ldB(kt + 2, (kt + 2) % 3); CP_COMMIT(); }
        compute(kt & 1, kt % 3);
        if (kt + 1 < KT) {
            stsA((kt + 1) & 1);
            if (kt + 2 < KT) ldgA(kt + 2);
        }
    }
    __syncthreads();

    // Epilogue: stage 64 x 264 halfs -> coalesced 16B stores
    __half* stg = reinterpret_cast<__half*>(smem);
    const int g = lane >> 2, tc = (lane & 3) * 2;
    #pragma unroll
    for (int mi = 0; mi < 2; mi++)
        #pragma unroll
        for (int nn = 0; nn < 8; nn++) {
            int row = wm * 32 + mi * 16 + g;
            int col = wn * 64 + (nn >> 1) * 16 + (nn & 1) * 8 + tc;
            float b0 = bias[col], b1 = bias[col + 1];
            *reinterpret_cast<__half2*>(stg + row * 264 + col) =
                __floats2half2_rn(acc[mi][nn][0] + b0, acc[mi][nn][1] + b1);
            *reinterpret_cast<__half2*>(stg + (row + 8) * 264 + col) =
                __floats2half2_rn(acc[mi][nn][2] + b0, acc[mi][nn][3] + b1);
        }
    __syncthreads();
    #pragma unroll
    for (int i = 0; i < 8; i++) {
        int idx = tid + i * 256;
        int row = idx >> 5, c = idx & 31;
        uint4 v = *reinterpret_cast<uint4*>(stg + row * 264 + c * 8);
        *reinterpret_cast<uint4*>(C + (size_t)(m0 + row) * 256 + c * 8) = v;
    }
}

// ---------------------------------------------------------------------------
// GEMM2: y[16384,2048] = fp32( h[16384,256] @ woT[2048,256]^T + bias )
// CTA 64x128, FULL K=256 resident. 8 warps (2x4, warp tile 32x32). 2 CTAs/SM.
// grid (16 n-tiles fastest, 256 m-tiles) -> h L2 reuse.
// ---------------------------------------------------------------------------
__global__ __launch_bounds__(256, 2) void gemm2_kernel(
    const __half* __restrict__ A, const __half* __restrict__ Bt,
    const float* __restrict__ bias, float* __restrict__ C)
{
    extern __shared__ char smem[];
    const uint32_t sb = smem_u32(smem);
    const int tid = threadIdx.x, wid = tid >> 5, lane = tid & 31;
    const int wm = wid >> 2, wn = wid & 3;   // 2 x 4 warps, warp tile 32x32
    const int n0 = blockIdx.x * 128;         // gridDim.x = 16  (n tiles, fastest)
    const int m0 = blockIdx.y * 64;          // gridDim.y = 256 (m tiles)

    auto Aoff = [&](int kt) { return sb + kt * 8192u; };            // 4 x 8KB
    auto Boff = [&](int kt) { return sb + 32768u + kt * 16384u; };  // 4 x 16KB

    auto ldTile = [&](int kt) {
        #pragma unroll
        for (int i = 0; i < 2; i++) {
            int c = tid + i * 256, row = c >> 3, cc = c & 7;
            CP_ASYNC16(Aoff(kt) + sw_off(row, cc),
                       A + (size_t)(m0 + row) * 256 + kt * 64 + cc * 8);
        }
        #pragma unroll
        for (int i = 0; i < 4; i++) {
            int c = tid + i * 256, row = c >> 3, cc = c & 7;
            CP_ASYNC16(Boff(kt) + sw_off(row, cc),
                       Bt + (size_t)(n0 + row) * 256 + kt * 64 + cc * 8);
        }
        CP_COMMIT();
    };

    float acc[2][4][4];
    #pragma unroll
    for (int mi = 0; mi < 2; mi++)
        #pragma unroll
        for (int nn = 0; nn < 4; nn++)
            #pragma unroll
            for (int j = 0; j < 4; j++) acc[mi][nn][j] = 0.f;

    uint32_t aBase[2], bBase[2]; int aX[2], bX[2];
    #pragma unroll
    for (int mi = 0; mi < 2; mi++) {
        int r = wm * 32 + mi * 16 + (lane & 15);
        aBase[mi] = (uint32_t)(r * 128); aX[mi] = r & 7;
    }
    #pragma unroll
    for (int ni = 0; ni < 2; ni++) {
        int r = wn * 32 + ni * 16 + (lane & 15);
        bBase[ni] = (uint32_t)(r * 128); bX[ni] = r & 7;
    }
    const int lhi = lane >> 4;

    auto compute = [&](int kt) {
        const uint32_t Ab = Aoff(kt), Bb = Boff(kt);
        #pragma unroll
        for (int ks = 0; ks < 4; ks++) {
            const int c = ks * 2 + lhi;
            uint32_t af[2][4], bf[2][4];
            #pragma unroll
            for (int mi = 0; mi < 2; mi++)
                ldsm4(af[mi], Ab + aBase[mi] + ((uint32_t)(c ^ aX[mi]) << 4));
            #pragma unroll
            for (int ni = 0; ni < 2; ni++)
                ldsm4(bf[ni], Bb + bBase[ni] + ((uint32_t)(c ^ bX[ni]) << 4));
            #pragma unroll
            for (int mi = 0; mi < 2; mi++)
                #pragma unroll
                for (int ni = 0; ni < 2; ni++) {
                    mma16816(acc[mi][2*ni],   af[mi], bf[ni][0], bf[ni][2]);
                    mma16816(acc[mi][2*ni+1], af[mi], bf[ni][1], bf[ni][3]);
                }
        }
    };

    ldTile(0); ldTile(1); ldTile(2); ldTile(3);
    cp_wait<3>(); __syncthreads(); compute(0);
    cp_wait<2>(); __syncthreads(); compute(1);
    cp_wait<1>(); __syncthreads(); compute(2);
    cp_wait<0>(); __syncthreads(); compute(3);

    const int g = lane >> 2, tc = (lane & 3) * 2;
    float bv[4][2];
    #pragma unroll
    for (int nn = 0; nn < 4; nn++) {
        int col = wn * 32 + (nn >> 1) * 16 + (nn & 1) * 8 + tc;
        bv[nn][0] = bias[n0 + col];
        bv[nn][1] = bias[n0 + col + 1];
    }
    __syncthreads();

    float* stg = reinterpret_cast<float*>(smem);
    #pragma unroll
    for (int mi = 0; mi < 2; mi++)
        #pragma unroll
        for (int nn = 0; nn < 4; nn++) {
            int row = wm * 32 + mi * 16 + g;
            int col = wn * 32 + (nn >> 1) * 16 + (nn & 1) * 8 + tc;
            *reinterpret_cast<float2*>(stg + row * 132 + col) =
                make_float2(acc[mi][nn][0] + bv[nn][0], acc[mi][nn][1] + bv[nn][1]);
            *reinterpret_cast<float2*>(stg + (row + 8) * 132 + col) =
                make_float2(acc[mi][nn][2] + bv[nn][0], acc[mi][nn][3] + bv[nn][1]);
        }
    __syncthreads();
    #pragma unroll
    for (int i = 0; i < 8; i++) {
        int idx = tid + i * 256;
        int row = idx >> 5, c = idx & 31;
        uint4 v = *reinterpret_cast<uint4*>(stg + row * 132 + c * 4);
        *reinterpret_cast<uint4*>(C + (size_t)(m0 + row) * 2048 + n0 + c * 4) = v;
    }
}

// ---------------------------------------------------------------------------
extern "C" void kernel_launch(void* const* d_in, const int* in_sizes, int n_in,
                              void* d_out, int out_size)
{
    const float* x     = (const float*)d_in[0];
    const float* w_in  = (const float*)d_in[1];
    const float* w_out = (const float*)d_in[2];
    const float* b_in  = (const float*)d_in[3];
    const float* b_out = (const float*)d_in[4];
    const float* s_in  = (const float*)d_in[5];
    const float* s_out = (const float*)d_in[6];

    __half *wiT, *woT, *h;
    cudaGetSymbolAddress((void**)&wiT, g_wiT);
    cudaGetSymbolAddress((void**)&woT, g_woT);
    cudaGetSymbolAddress((void**)&h,   g_h);

    constexpr int SMEM1 = 16384 + 3 * 32768;  // 114688 (A 2x8KB + B 3x32KB)
    constexpr int SMEM2 = 32768 + 65536;      // 98304  (A 4x8KB + B 4x16KB)
    cudaFuncSetAttribute(gemm1_kernel, cudaFuncAttributeMaxDynamicSharedMemorySize, SMEM1);
    cudaFuncSetAttribute(gemm2_kernel, cudaFuncAttributeMaxDynamicSharedMemorySize, SMEM2);

    // Prep w_in only (fine-grained, latency-optimized); w_out preps inside gemm1
    prep_wi_kernel<<<256, 256>>>(w_in, s_in, wiT);

    // GEMM1 (blocks 0-255) + w_out prep riders (blocks 256-287): one wave @ 2/SM
    gemm1_kernel<<<dim3(288), 256, SMEM1>>>(x, wiT, b_in, h, w_out, s_out, woT);

    // GEMM2: grid (16 n fastest, 256 m) for h L2 reuse
    gemm2_kernel<<<dim3(16, 256), 256, SMEM2>>>(h, woT, b_out, (float*)d_out);
}